// round 5
// baseline (speedup 1.0000x reference)
#include <cuda_runtime.h>
#include <cuda_bf16.h>
#include <math.h>
#include <stdint.h>

#define B_   8
#define S_   1024
#define D_   2048
#define H_   16
#define HD_  128
#define MTOT (B_*S_)
#define BH_  (B_*H_)

// split storage: [hi | lo], logical K is 3x via index wrap in the GEMM
__device__ __nv_bfloat16 g_xs  [(size_t)MTOT*2*D_];
__device__ __nv_bfloat16 g_wqs [(size_t)D_*2*D_];
__device__ __nv_bfloat16 g_wks [(size_t)D_*2*D_];
__device__ __nv_bfloat16 g_wvs [(size_t)D_*2*D_];
__device__ __nv_bfloat16 g_wos [(size_t)D_*2*D_];
__device__ __nv_bfloat16 g_qs  [(size_t)BH_*S_*2*HD_];
__device__ __nv_bfloat16 g_ks  [(size_t)BH_*S_*2*HD_];
__device__ float         g_v   [(size_t)MTOT*D_];
__device__ __nv_bfloat16 g_vt  [(size_t)BH_*HD_*2*S_];
__device__ float         g_p   [(size_t)BH_*S_*S_];
__device__ __nv_bfloat16 g_ps  [(size_t)BH_*S_*2*S_];
__device__ __nv_bfloat16 g_ctxs[(size_t)MTOT*2*D_];
__device__ float g_cos[(size_t)S_*(D_/2)];
__device__ float g_sin[(size_t)S_*(D_/2)];

__device__ __forceinline__ uint32_t smem_u32(const void* p) {
    uint32_t a;
    asm("{ .reg .u64 t; cvta.to.shared.u64 t, %1; cvt.u32.u64 %0, t; }" : "=r"(a) : "l"(p));
    return a;
}
__device__ __forceinline__ void cp16(uint32_t dst, const void* src) {
    asm volatile("cp.async.cg.shared.global [%0], [%1], 16;" :: "r"(dst), "l"(src));
}
#define CP_COMMIT() asm volatile("cp.async.commit_group;" ::: "memory")
#define CP_WAIT2()  asm volatile("cp.async.wait_group 2;" ::: "memory")

#define LDSM4(r, addr)                                                         \
    asm volatile("ldmatrix.sync.aligned.m8n8.x4.shared.b16 {%0,%1,%2,%3}, [%4];" \
        : "=r"((r)[0]),"=r"((r)[1]),"=r"((r)[2]),"=r"((r)[3]) : "r"(addr))

#define MMA(d, a, b0r, b1r)                                                    \
    asm volatile("mma.sync.aligned.m16n8k16.row.col.f32.bf16.bf16.f32 "        \
        "{%0,%1,%2,%3}, {%4,%5,%6,%7}, {%8,%9}, {%0,%1,%2,%3};"                \
        : "+f"((d)[0]),"+f"((d)[1]),"+f"((d)[2]),"+f"((d)[3])                  \
        : "r"((a)[0]),"r"((a)[1]),"r"((a)[2]),"r"((a)[3]), "r"(b0r),"r"(b1r))

__device__ __forceinline__ uint32_t pack_hi(float a, float b, float* la, float* lb) {
    __nv_bfloat162 p;
    p.x = __float2bfloat16(a); p.y = __float2bfloat16(b);
    *la = a - __bfloat162float(p.x);
    *lb = b - __bfloat162float(p.y);
    return *(uint32_t*)&p;
}
__device__ __forceinline__ uint32_t pack_bf2(float a, float b) {
    __nv_bfloat162 p;
    p.x = __float2bfloat16(a); p.y = __float2bfloat16(b);
    return *(uint32_t*)&p;
}

// smem tile: ROWS x 32 bf16 (64B/row), chunk swizzle ch^((row>>1)&3)
template <int ROWS>
__device__ __forceinline__ void load_tile(uint32_t sbase, const __nv_bfloat16* g,
                                          int ld, int t) {
#pragma unroll
    for (int i = 0; i < ROWS/64; i++) {
        int lin = t + 256*i, row = lin >> 2, ch = lin & 3;
        uint32_t sw = row*64 + ((ch ^ ((row >> 1) & 3)) << 4);
        cp16(sbase + sw, g + (size_t)row*ld + ch*8);
    }
}

// ===========================================================================
// mma.sync bf16 GEMM: C[M,TNgrid] = alpha * A'[M,K3] @ B'[N,K3]^T
// CTA 128xTN, BK=32, 4-stage cp.async, 8 warps (2M x 4N), warp 64x(TN/4).
// Logical split K3 = 3K mapped onto [hi|lo] storage:
//   A col = k - (k>=wA ? wA : 0)   (hi,hi,lo)
//   B col = k - (k>=wB ? wB : 0)   (hi,lo,hi)
// EPI 0: fp32. EPI 1: RoPE+2split -> [b,h,s,256]. EPI 2: 2split -> [8192,4096]
// ===========================================================================
template <int EPI, int TN>
__global__ __launch_bounds__(256) void tgemm(
    const __nv_bfloat16* __restrict__ A, int lda,
    const __nv_bfloat16* __restrict__ B, int ldb,
    float* __restrict__ Cf, __nv_bfloat16* __restrict__ Cs, int ldc,
    int K3, int wA, int wB, float alpha,
    size_t sA, size_t sB, size_t sC, int offLo,
    const float* __restrict__ cosT, const float* __restrict__ sinT)
{
    constexpr int WN  = TN/4;      // warp N
    constexpr int NF  = WN/8;      // n8 frags per warp
    constexpr int NB  = WN/16;     // B ldmatrix per ks
    constexpr int STG = 8192 + TN*64;
    extern __shared__ __align__(1024) char dsm[];
    const uint32_t smem0 = smem_u32(dsm);

    const int t = threadIdx.x, lane = t & 31, w = t >> 5;
    const int wm = w >> 2, wn = w & 3;
    const int z = blockIdx.z;
    const int m0 = blockIdx.y * 128, n0 = blockIdx.x * TN;
    const __nv_bfloat16* At = A + (size_t)z*sA + (size_t)m0*lda;
    const __nv_bfloat16* Bt = B + (size_t)z*sB + (size_t)n0*ldb;

    float acc[4][NF][4];
#pragma unroll
    for (int i = 0; i < 4; i++)
#pragma unroll
        for (int j = 0; j < NF; j++)
#pragma unroll
            for (int c = 0; c < 4; c++) acc[i][j][c] = 0.f;

    const int NS = K3 / 32;
#pragma unroll
    for (int st = 0; st < 3; st++) {
        int k0 = st*32;
        int ka = k0 - (k0 >= wA ? wA : 0);
        int kb = k0 - (k0 >= wB ? wB : 0);
        load_tile<128>(smem0 + st*STG,        At + ka, lda, t);
        load_tile<TN >(smem0 + st*STG + 8192, Bt + kb, ldb, t);
        CP_COMMIT();
    }
    const int l15 = lane & 15, l16 = lane >> 4;

    for (int s = 0; s < NS; s++) {
        CP_WAIT2();
        __syncthreads();
        if (s + 3 < NS) {
            const int st = (s + 3) & 3;
            int k0 = (s+3)*32;
            int ka = k0 - (k0 >= wA ? wA : 0);
            int kb = k0 - (k0 >= wB ? wB : 0);
            load_tile<128>(smem0 + st*STG,        At + ka, lda, t);
            load_tile<TN >(smem0 + st*STG + 8192, Bt + kb, ldb, t);
        }
        CP_COMMIT();

        const uint32_t sAb = smem0 + (s & 3)*STG;
        const uint32_t sBb = sAb + 8192;
#pragma unroll
        for (int ks = 0; ks < 2; ks++) {
            uint32_t a[4][4], b[NB][4];
            const int ch = ks*2 + l16;
#pragma unroll
            for (int mi = 0; mi < 4; mi++) {
                int r = wm*64 + mi*16 + l15;
                LDSM4(a[mi], sAb + r*64 + ((ch ^ ((r >> 1) & 3)) << 4));
            }
#pragma unroll
            for (int nj = 0; nj < NB; nj++) {
                int r = wn*WN + nj*16 + l15;
                LDSM4(b[nj], sBb + r*64 + ((ch ^ ((r >> 1) & 3)) << 4));
            }
#pragma unroll
            for (int mi = 0; mi < 4; mi++)
#pragma unroll
                for (int ni = 0; ni < NF; ni++)
                    MMA(acc[mi][ni], a[mi], b[ni >> 1][ni & 1], b[ni >> 1][(ni & 1) + 2]);
        }
    }

    // ------------------------------ epilogue -------------------------------
    const int gi = lane >> 2, t4 = lane & 3;
#pragma unroll
    for (int mi = 0; mi < 4; mi++) {
#pragma unroll
        for (int half = 0; half < 2; half++) {
            const int row = m0 + wm*64 + mi*16 + gi + half*8;
            if (EPI == 0) {
                float* dst = Cf + (size_t)z*sC + (size_t)row*ldc + n0;
#pragma unroll
                for (int ni = 0; ni < NF; ni++) {
                    int lc = wn*WN + ni*8 + t4*2;
                    *(float2*)(dst + lc) = make_float2(acc[mi][ni][half*2]   * alpha,
                                                       acc[mi][ni][half*2+1] * alpha);
                }
            } else if (EPI == 1) {
                const int pos = row & (S_-1), bb = row >> 10;
                const float* cr = cosT + (size_t)pos*(D_/2);
                const float* sr = sinT + (size_t)pos*(D_/2);
#pragma unroll
                for (int ni = 0; ni < NF; ni++) {
                    int gc = n0 + wn*WN + ni*8 + t4*2;     // global hidden col
                    int h = gc >> 7, ch128 = gc & 127;
                    int fi = gc >> 1;
                    float c = cr[fi], sn = sr[fi];
                    float v0 = acc[mi][ni][half*2], v1 = acc[mi][ni][half*2+1];
                    float r0 = v0*c - v1*sn, r1 = v0*sn + v1*c;
                    float la, lb;
                    uint32_t hi = pack_hi(r0, r1, &la, &lb);
                    uint32_t lo = pack_bf2(la, lb);
                    __nv_bfloat16* dst = Cs + ((size_t)(bb*H_ + h)*S_ + pos)*(2*HD_) + ch128;
                    *(uint32_t*)(dst)         = hi;
                    *(uint32_t*)(dst + offLo) = lo;
                }
            } else {
                const int bb = z >> 4, h = z & 15;
                __nv_bfloat16* dst = Cs + (size_t)(bb*S_ + row)*(2*D_) + h*HD_;
#pragma unroll
                for (int ni = 0; ni < NF; ni++) {
                    int lc = wn*WN + ni*8 + t4*2;
                    float la, lb;
                    uint32_t hi = pack_hi(acc[mi][ni][half*2], acc[mi][ni][half*2+1],
                                          &la, &lb);
                    uint32_t lo = pack_bf2(la, lb);
                    *(uint32_t*)(dst + lc)         = hi;
                    *(uint32_t*)(dst + lc + offLo) = lo;
                }
            }
        }
    }
}

// fp32 [R,2048] -> bf16 [R,4096] = [hi|lo]
__global__ __launch_bounds__(256) void conv_split_k(
    const float4* __restrict__ in, __nv_bfloat16* __restrict__ out, int nchunk)
{
    int i = blockIdx.x*256 + threadIdx.x;
    if (i >= nchunk) return;
    int r = i >> 8, c = (i & 255)*8;
    float4 v0 = in[i*2], v1 = in[i*2+1];
    float f[8] = {v0.x,v0.y,v0.z,v0.w,v1.x,v1.y,v1.z,v1.w};
    uint32_t hh[4], ll[4];
#pragma unroll
    for (int j = 0; j < 4; j++) {
        float la, lb;
        hh[j] = pack_hi(f[2*j], f[2*j+1], &la, &lb);
        ll[j] = pack_bf2(la, lb);
    }
    __nv_bfloat16* dst = out + (size_t)r*(2*D_) + c;
    *(uint4*)dst        = make_uint4(hh[0],hh[1],hh[2],hh[3]);
    *(uint4*)(dst + D_) = make_uint4(ll[0],ll[1],ll[2],ll[3]);
}

// V [b,s,h,hd] fp32 -> VT [bh,n,2048] = [hi|lo]
__global__ __launch_bounds__(256) void vsplit_k(
    const float* __restrict__ V, __nv_bfloat16* __restrict__ VT)
{
    __shared__ float tile[32][33];
    const int bh = blockIdx.x, b = bh >> 4, h = bh & 15;
    const int k0 = blockIdx.y*32, n0 = blockIdx.z*32;
    const int r = threadIdx.x >> 5, c = threadIdx.x & 31;
#pragma unroll
    for (int i = 0; i < 4; i++)
        tile[r + i*8][c] = V[((size_t)(b*S_ + k0 + r + i*8))*D_ + h*HD_ + n0 + c];
    __syncthreads();
#pragma unroll
    for (int i = 0; i < 4; i++) {
        int n = n0 + r + i*8;
        float v = tile[c][r + i*8];
        __nv_bfloat16 hi = __float2bfloat16(v);
        __nv_bfloat16 lo = __float2bfloat16(v - __bfloat162float(hi));
        __nv_bfloat16* dst = VT + ((size_t)bh*HD_ + n)*(2*S_) + k0 + c;
        dst[0]  = hi;
        dst[S_] = lo;
    }
}

// softmax over 1024 + split-write [row,2048] = [hi|lo]
__global__ __launch_bounds__(256) void softmax_split_k(
    const float* __restrict__ P, __nv_bfloat16* __restrict__ PS)
{
    const float4* row = (const float4*)(P + (size_t)blockIdx.x*S_);
    const int t = threadIdx.x;
    __shared__ float red[256];
    float4 v = row[t];
    float m = fmaxf(fmaxf(v.x, v.y), fmaxf(v.z, v.w));
    red[t] = m; __syncthreads();
    for (int s = 128; s > 0; s >>= 1) { if (t < s) red[t] = fmaxf(red[t], red[t+s]); __syncthreads(); }
    m = red[0]; __syncthreads();
    v.x = expf(v.x - m); v.y = expf(v.y - m);
    v.z = expf(v.z - m); v.w = expf(v.w - m);
    red[t] = v.x + v.y + v.z + v.w; __syncthreads();
    for (int s = 128; s > 0; s >>= 1) { if (t < s) red[t] += red[t+s]; __syncthreads(); }
    const float inv = 1.f / red[0];
    float f[4] = { v.x*inv, v.y*inv, v.z*inv, v.w*inv };
    float la0, lb0, la1, lb1;
    uint32_t h0 = pack_hi(f[0], f[1], &la0, &lb0);
    uint32_t h1 = pack_hi(f[2], f[3], &la1, &lb1);
    __nv_bfloat16* dst = PS + (size_t)blockIdx.x*(2*S_) + t*4;
    *(uint2*)dst        = make_uint2(h0, h1);
    *(uint2*)(dst + S_) = make_uint2(pack_bf2(la0, lb0), pack_bf2(la1, lb1));
}

__global__ void rope_tables_k(float* __restrict__ cosT, float* __restrict__ sinT) {
    int idx = blockIdx.x*blockDim.x + threadIdx.x;
    int pos = idx >> 10, f = idx & 1023;
    double inv = exp(-(double)(2*f)/(double)D_ * 9.210340371976184);
    double a = (double)pos * inv;
    cosT[idx] = (float)cos(a);
    sinT[idx] = (float)sin(a);
}

extern "C" void kernel_launch(void* const* d_in, const int* in_sizes, int n_in,
                              void* d_out, int out_size) {
    const float* x  = (const float*)d_in[0];
    const float* wq = (const float*)d_in[1];
    const float* wk = (const float*)d_in[2];
    const float* wv = (const float*)d_in[3];
    const float* wo = (const float*)d_in[4];
    float* out = (float*)d_out;

    __nv_bfloat16 *xs,*wqs,*wks,*wvs,*wos,*qs,*ks,*vt,*ps,*ctxs;
    float *v,*p,*ct,*st;
    cudaGetSymbolAddress((void**)&xs, g_xs);
    cudaGetSymbolAddress((void**)&wqs, g_wqs);
    cudaGetSymbolAddress((void**)&wks, g_wks);
    cudaGetSymbolAddress((void**)&wvs, g_wvs);
    cudaGetSymbolAddress((void**)&wos, g_wos);
    cudaGetSymbolAddress((void**)&qs, g_qs);
    cudaGetSymbolAddress((void**)&ks, g_ks);
    cudaGetSymbolAddress((void**)&v, g_v);
    cudaGetSymbolAddress((void**)&vt, g_vt);
    cudaGetSymbolAddress((void**)&p, g_p);
    cudaGetSymbolAddress((void**)&ps, g_ps);
    cudaGetSymbolAddress((void**)&ctxs, g_ctxs);
    cudaGetSymbolAddress((void**)&ct, g_cos);
    cudaGetSymbolAddress((void**)&st, g_sin);

    const int SM256 = 4*(8192 + 256*64);   // 98304
    const int SM128 = 4*(8192 + 128*64);   // 65536
    cudaFuncSetAttribute(tgemm<0,256>, cudaFuncAttributeMaxDynamicSharedMemorySize, SM256);
    cudaFuncSetAttribute(tgemm<1,256>, cudaFuncAttributeMaxDynamicSharedMemorySize, SM256);
    cudaFuncSetAttribute(tgemm<2,128>, cudaFuncAttributeMaxDynamicSharedMemorySize, SM128);

    rope_tables_k<<<(S_*(D_/2))/256, 256>>>(ct, st);

    const int xn = MTOT*D_/8, wn = D_*D_/8;
    conv_split_k<<<xn/256, 256>>>((const float4*)x,  xs,  xn);
    conv_split_k<<<wn/256, 256>>>((const float4*)wq, wqs, wn);
    conv_split_k<<<wn/256, 256>>>((const float4*)wk, wks, wn);
    conv_split_k<<<wn/256, 256>>>((const float4*)wv, wvs, wn);
    conv_split_k<<<wn/256, 256>>>((const float4*)wo, wos, wn);

    // projections: [8192,2048], logical K=6144, wA=2048, wB=4096
    dim3 gProj(D_/256, MTOT/128, 1);   // (8, 64)
    tgemm<1,256><<<gProj, 256, SM256>>>(xs, 2*D_, wqs, 2*D_, nullptr, qs, 0,
                                        3*D_, D_, 2*D_, 1.f, 0, 0, 0, HD_, ct, st);
    tgemm<1,256><<<gProj, 256, SM256>>>(xs, 2*D_, wks, 2*D_, nullptr, ks, 0,
                                        3*D_, D_, 2*D_, 1.f, 0, 0, 0, HD_, ct, st);
    tgemm<0,256><<<gProj, 256, SM256>>>(xs, 2*D_, wvs, 2*D_, v, nullptr, D_,
                                        3*D_, D_, 2*D_, 1.f, 0, 0, 0, 0, nullptr, nullptr);

    vsplit_k<<<dim3(BH_, 32, 4), 256>>>(v, vt);

    // scores: per (b,h) [1024,1024], logical K=384, wA=128, wB=256
    const float alpha = 1.0f / sqrtf((float)D_);
    tgemm<0,256><<<dim3(4, 8, BH_), 256, SM256>>>(qs, 2*HD_, ks, 2*HD_, p, nullptr, S_,
                                                  3*HD_, HD_, 2*HD_, alpha,
                                                  (size_t)S_*2*HD_, (size_t)S_*2*HD_,
                                                  (size_t)S_*S_, 0, nullptr, nullptr);

    softmax_split_k<<<BH_*S_, 256>>>(p, ps);

    // ctx: per (b,h) [1024,128], logical K=3072, wA=1024, wB=2048
    tgemm<2,128><<<dim3(1, 8, BH_), 256, SM128>>>(ps, 2*S_, vt, 2*S_, nullptr, ctxs, 0,
                                                  3*S_, S_, 2*S_, 1.f,
                                                  (size_t)S_*2*S_, (size_t)HD_*2*S_, 0,
                                                  D_, nullptr, nullptr);

    // out = ctx @ wo^T
    tgemm<0,256><<<gProj, 256, SM256>>>(ctxs, 2*D_, wos, 2*D_, out, nullptr, D_,
                                        3*D_, D_, 2*D_, 1.f, 0, 0, 0, 0, nullptr, nullptr);
}

// round 7
// speedup vs baseline: 1.2325x; 1.2325x over previous
#include <cuda_runtime.h>
#include <cuda_bf16.h>
#include <math.h>
#include <stdint.h>

#define B_   8
#define S_   1024
#define D_   2048
#define H_   16
#define HD_  128
#define MTOT (B_*S_)
#define BH_  (B_*H_)

// split storage: [hi | lo] planes; logical K=3K via index wrap in the GEMM
__device__ __nv_bfloat16 g_xs  [(size_t)MTOT*2*D_];
__device__ __nv_bfloat16 g_wqs [(size_t)D_*2*D_];
__device__ __nv_bfloat16 g_wks [(size_t)D_*2*D_];
__device__ __nv_bfloat16 g_wvs [(size_t)D_*2*D_];
__device__ __nv_bfloat16 g_wos [(size_t)D_*2*D_];
__device__ __nv_bfloat16 g_qs  [(size_t)BH_*S_*2*HD_];
__device__ __nv_bfloat16 g_ks  [(size_t)BH_*S_*2*HD_];
__device__ float         g_v   [(size_t)MTOT*D_];
__device__ __nv_bfloat16 g_vt  [(size_t)BH_*HD_*2*S_];
__device__ float         g_p   [(size_t)BH_*S_*S_];
__device__ __nv_bfloat16 g_ps  [(size_t)BH_*S_*2*S_];
__device__ __nv_bfloat16 g_ctxs[(size_t)MTOT*2*D_];
__device__ float g_cos[(size_t)S_*(D_/2)];
__device__ float g_sin[(size_t)S_*(D_/2)];

__device__ __forceinline__ uint32_t smem_u32(const void* p) {
    uint32_t a;
    asm("{ .reg .u64 t; cvta.to.shared.u64 t, %1; cvt.u32.u64 %0, t; }" : "=r"(a) : "l"(p));
    return a;
}
__device__ __forceinline__ void cp16(uint32_t dst, const void* src) {
    asm volatile("cp.async.cg.shared.global [%0], [%1], 16;" :: "r"(dst), "l"(src));
}
#define CP_COMMIT() asm volatile("cp.async.commit_group;" ::: "memory")
#define CP_WAIT2()  asm volatile("cp.async.wait_group 2;" ::: "memory")

#define LDSM4(r, addr)                                                         \
    asm volatile("ldmatrix.sync.aligned.m8n8.x4.shared.b16 {%0,%1,%2,%3}, [%4];" \
        : "=r"((r)[0]),"=r"((r)[1]),"=r"((r)[2]),"=r"((r)[3]) : "r"(addr))

#define MMA(d, a, b0r, b1r)                                                    \
    asm volatile("mma.sync.aligned.m16n8k16.row.col.f32.bf16.bf16.f32 "        \
        "{%0,%1,%2,%3}, {%4,%5,%6,%7}, {%8,%9}, {%0,%1,%2,%3};"                \
        : "+f"((d)[0]),"+f"((d)[1]),"+f"((d)[2]),"+f"((d)[3])                  \
        : "r"((a)[0]),"r"((a)[1]),"r"((a)[2]),"r"((a)[3]), "r"(b0r),"r"(b1r))

__device__ __forceinline__ uint32_t pack_hi(float a, float b, float* la, float* lb) {
    __nv_bfloat162 p;
    p.x = __float2bfloat16(a); p.y = __float2bfloat16(b);
    *la = a - __bfloat162float(p.x);
    *lb = b - __bfloat162float(p.y);
    return *(uint32_t*)&p;
}
__device__ __forceinline__ uint32_t pack_bf2(float a, float b) {
    __nv_bfloat162 p;
    p.x = __float2bfloat16(a); p.y = __float2bfloat16(b);
    return *(uint32_t*)&p;
}

// smem tile: 128 rows x 32 bf16 (64B/row), chunk swizzle ch^((row>>1)&3)
__device__ __forceinline__ void load_tile(uint32_t sbase, const __nv_bfloat16* g,
                                          int ld, int t) {
#pragma unroll
    for (int i = 0; i < 2; i++) {
        int lin = t + 256*i, row = lin >> 2, ch = lin & 3;
        uint32_t sw = row*64 + ((ch ^ ((row >> 1) & 3)) << 4);
        cp16(sbase + sw, g + (size_t)row*ld + ch*8);
    }
}

// ===========================================================================
// mma.sync bf16 GEMM: C = alpha * A'[M,K3] @ B'[N,K3]^T
// CTA 128x128, BK=32, 4-stage cp.async, 8 warps (2Mx4N), warp 64x32  (R4 cfg)
// Logical K3 = 3K on [hi|lo] storage (width 2K):
//   A col = k - (k>=wA ? wA : 0)   -> pattern (hi, hi, lo),  wA = K
//   B col = k - (k>=wB ? wB : 0)   -> pattern (hi, lo, hi),  wB = 2K
// EPI 0: fp32. EPI 1: RoPE+split -> [b,h,s,2*128]. EPI 2: split -> [8192,2*2048]
// ===========================================================================
template <int EPI>
__global__ __launch_bounds__(256) void tgemm(
    const __nv_bfloat16* __restrict__ A, int lda,
    const __nv_bfloat16* __restrict__ B, int ldb,
    float* __restrict__ Cf, __nv_bfloat16* __restrict__ Cs, int ldc,
    int K3, int wA, int wB, float alpha,
    size_t sA, size_t sB, size_t sC,
    const float* __restrict__ cosT, const float* __restrict__ sinT)
{
    extern __shared__ __align__(1024) char dsm[];
    const uint32_t smem0 = smem_u32(dsm);

    const int t = threadIdx.x, lane = t & 31, w = t >> 5;
    const int wm = w >> 2, wn = w & 3;
    const int z = blockIdx.z;
    const int m0 = blockIdx.y * 128, n0 = blockIdx.x * 128;
    const __nv_bfloat16* At = A + (size_t)z*sA + (size_t)m0*lda;
    const __nv_bfloat16* Bt = B + (size_t)z*sB + (size_t)n0*ldb;

    float acc[4][4][4];
#pragma unroll
    for (int i = 0; i < 4; i++)
#pragma unroll
        for (int j = 0; j < 4; j++)
#pragma unroll
            for (int c = 0; c < 4; c++) acc[i][j][c] = 0.f;

    const int NS = K3 / 32;
#pragma unroll
    for (int st = 0; st < 3; st++) {
        int k0 = st*32;
        int ka = k0 - (k0 >= wA ? wA : 0);
        int kb = k0 - (k0 >= wB ? wB : 0);
        load_tile(smem0 + st*16384,        At + ka, lda, t);
        load_tile(smem0 + st*16384 + 8192, Bt + kb, ldb, t);
        CP_COMMIT();
    }
    const int l15 = lane & 15, l16 = lane >> 4;

    for (int s = 0; s < NS; s++) {
        CP_WAIT2();
        __syncthreads();
        if (s + 3 < NS) {
            const int st = (s + 3) & 3;
            int k0 = (s+3)*32;
            int ka = k0 - (k0 >= wA ? wA : 0);
            int kb = k0 - (k0 >= wB ? wB : 0);
            load_tile(smem0 + st*16384,        At + ka, lda, t);
            load_tile(smem0 + st*16384 + 8192, Bt + kb, ldb, t);
        }
        CP_COMMIT();

        const uint32_t sAb = smem0 + (s & 3)*16384;
        const uint32_t sBb = sAb + 8192;
#pragma unroll
        for (int ks = 0; ks < 2; ks++) {
            uint32_t a[4][4], b[2][4];
            const int ch = ks*2 + l16;
#pragma unroll
            for (int mi = 0; mi < 4; mi++) {
                int r = wm*64 + mi*16 + l15;
                LDSM4(a[mi], sAb + r*64 + ((ch ^ ((r >> 1) & 3)) << 4));
            }
#pragma unroll
            for (int nj = 0; nj < 2; nj++) {
                int r = wn*32 + nj*16 + l15;
                LDSM4(b[nj], sBb + r*64 + ((ch ^ ((r >> 1) & 3)) << 4));
            }
#pragma unroll
            for (int mi = 0; mi < 4; mi++)
#pragma unroll
                for (int ni = 0; ni < 4; ni++)
                    MMA(acc[mi][ni], a[mi], b[ni >> 1][ni & 1], b[ni >> 1][(ni & 1) + 2]);
        }
    }

    // ------------------------------ epilogue -------------------------------
    const int gi = lane >> 2, t4 = lane & 3;
#pragma unroll
    for (int mi = 0; mi < 4; mi++) {
#pragma unroll
        for (int half = 0; half < 2; half++) {
            const int row = m0 + wm*64 + mi*16 + gi + half*8;
            if (EPI == 0) {
                float* dst = Cf + (size_t)z*sC + (size_t)row*ldc + n0;
#pragma unroll
                for (int ni = 0; ni < 4; ni++) {
                    int lc = wn*32 + ni*8 + t4*2;
                    *(float2*)(dst + lc) = make_float2(acc[mi][ni][half*2]   * alpha,
                                                       acc[mi][ni][half*2+1] * alpha);
                }
            } else if (EPI == 1) {
                const int pos = row & (S_-1), bb = row >> 10;
                const float* cr = cosT + (size_t)pos*(D_/2);
                const float* sr = sinT + (size_t)pos*(D_/2);
#pragma unroll
                for (int ni = 0; ni < 4; ni++) {
                    int gc = n0 + wn*32 + ni*8 + t4*2;   // global hidden col
                    int h = gc >> 7, ch128 = gc & 127;
                    int fi = gc >> 1;
                    float c = cr[fi], sn = sr[fi];
                    float v0 = acc[mi][ni][half*2], v1 = acc[mi][ni][half*2+1];
                    float r0 = v0*c - v1*sn, r1 = v0*sn + v1*c;
                    float la, lb;
                    uint32_t hi = pack_hi(r0, r1, &la, &lb);
                    uint32_t lo = pack_bf2(la, lb);
                    __nv_bfloat16* dst = Cs + ((size_t)(bb*H_ + h)*S_ + pos)*(2*HD_) + ch128;
                    *(uint32_t*)(dst)       = hi;
                    *(uint32_t*)(dst + HD_) = lo;
                }
            } else {
                const int bb = z >> 4, h = z & 15;
                __nv_bfloat16* dst = Cs + (size_t)(bb*S_ + row)*(2*D_) + h*HD_;
#pragma unroll
                for (int ni = 0; ni < 4; ni++) {
                    int lc = wn*32 + ni*8 + t4*2;
                    float la, lb;
                    uint32_t hi = pack_hi(acc[mi][ni][half*2], acc[mi][ni][half*2+1],
                                          &la, &lb);
                    uint32_t lo = pack_bf2(la, lb);
                    *(uint32_t*)(dst + lc)      = hi;
                    *(uint32_t*)(dst + lc + D_) = lo;
                }
            }
        }
    }
}

// fp32 -> [hi|lo] bf16 for x + 4 weights in ONE launch (row-partitioned)
__global__ __launch_bounds__(256) void conv_split_all(
    const float4* __restrict__ x,  __nv_bfloat16* __restrict__ xs,
    const float4* __restrict__ w0, __nv_bfloat16* __restrict__ o0,
    const float4* __restrict__ w1, __nv_bfloat16* __restrict__ o1,
    const float4* __restrict__ w2, __nv_bfloat16* __restrict__ o2,
    const float4* __restrict__ w3, __nv_bfloat16* __restrict__ o3)
{
    int i = blockIdx.x*256 + threadIdx.x;           // chunk of 8 elems
    int row = i >> 8, cj = i & 255;                 // 256 chunks per 2048-row
    const float4* src; __nv_bfloat16* dst; int r;
    if (row < MTOT)            { src = x;  dst = xs; r = row; }
    else {
        int wrow = row - MTOT, wi = wrow >> 11; r = wrow & (D_-1);
        if      (wi == 0) { src = w0; dst = o0; }
        else if (wi == 1) { src = w1; dst = o1; }
        else if (wi == 2) { src = w2; dst = o2; }
        else              { src = w3; dst = o3; }
    }
    // row = 512 float4s; chunk cj covers float4 indices [cj*2, cj*2+2)
    float4 v0 = src[(size_t)r*512 + cj*2], v1 = src[(size_t)r*512 + cj*2 + 1];
    float f[8] = {v0.x,v0.y,v0.z,v0.w,v1.x,v1.y,v1.z,v1.w};
    uint32_t hh[4], ll[4];
#pragma unroll
    for (int j = 0; j < 4; j++) {
        float la, lb;
        hh[j] = pack_hi(f[2*j], f[2*j+1], &la, &lb);
        ll[j] = pack_bf2(la, lb);
    }
    __nv_bfloat16* d = dst + (size_t)r*(2*D_) + cj*8;
    *(uint4*)d        = make_uint4(hh[0],hh[1],hh[2],hh[3]);
    *(uint4*)(d + D_) = make_uint4(ll[0],ll[1],ll[2],ll[3]);
}

// V [b,s,h,hd] fp32 -> VT [bh,n,2*1024] = [hi|lo]
__global__ __launch_bounds__(256) void vsplit_k(
    const float* __restrict__ V, __nv_bfloat16* __restrict__ VT)
{
    __shared__ float tile[32][33];
    const int bh = blockIdx.x, b = bh >> 4, h = bh & 15;
    const int k0 = blockIdx.y*32, n0 = blockIdx.z*32;
    const int r = threadIdx.x >> 5, c = threadIdx.x & 31;
#pragma unroll
    for (int i = 0; i < 4; i++)
        tile[r + i*8][c] = V[((size_t)(b*S_ + k0 + r + i*8))*D_ + h*HD_ + n0 + c];
    __syncthreads();
#pragma unroll
    for (int i = 0; i < 4; i++) {
        int n = n0 + r + i*8;
        float v = tile[c][r + i*8];
        __nv_bfloat16 hi = __float2bfloat16(v);
        __nv_bfloat16 lo = __float2bfloat16(v - __bfloat162float(hi));
        __nv_bfloat16* dst = VT + ((size_t)bh*HD_ + n)*(2*S_) + k0 + c;
        dst[0]  = hi;
        dst[S_] = lo;
    }
}

// softmax over 1024 + split-write [row, 2*1024] = [hi|lo]
__global__ __launch_bounds__(256) void softmax_split_k(
    const float* __restrict__ P, __nv_bfloat16* __restrict__ PS)
{
    const float4* row = (const float4*)(P + (size_t)blockIdx.x*S_);
    const int t = threadIdx.x;
    __shared__ float red[256];
    float4 v = row[t];
    float m = fmaxf(fmaxf(v.x, v.y), fmaxf(v.z, v.w));
    red[t] = m; __syncthreads();
    for (int s = 128; s > 0; s >>= 1) { if (t < s) red[t] = fmaxf(red[t], red[t+s]); __syncthreads(); }
    m = red[0]; __syncthreads();
    v.x = expf(v.x - m); v.y = expf(v.y - m);
    v.z = expf(v.z - m); v.w = expf(v.w - m);
    red[t] = v.x + v.y + v.z + v.w; __syncthreads();
    for (int s = 128; s > 0; s >>= 1) { if (t < s) red[t] += red[t+s]; __syncthreads(); }
    const float inv = 1.f / red[0];
    float f[4] = { v.x*inv, v.y*inv, v.z*inv, v.w*inv };
    float la0, lb0, la1, lb1;
    uint32_t h0 = pack_hi(f[0], f[1], &la0, &lb0);
    uint32_t h1 = pack_hi(f[2], f[3], &la1, &lb1);
    __nv_bfloat16* dst = PS + (size_t)blockIdx.x*(2*S_) + t*4;
    *(uint2*)dst        = make_uint2(h0, h1);
    *(uint2*)(dst + S_) = make_uint2(pack_bf2(la0, lb0), pack_bf2(la1, lb1));
}

__global__ void rope_tables_k(float* __restrict__ cosT, float* __restrict__ sinT) {
    int idx = blockIdx.x*blockDim.x + threadIdx.x;
    int pos = idx >> 10, f = idx & 1023;
    double inv = exp(-(double)(2*f)/(double)D_ * 9.210340371976184);
    double a = (double)pos * inv;
    cosT[idx] = (float)cos(a);
    sinT[idx] = (float)sin(a);
}

extern "C" void kernel_launch(void* const* d_in, const int* in_sizes, int n_in,
                              void* d_out, int out_size) {
    const float* x  = (const float*)d_in[0];
    const float* wq = (const float*)d_in[1];
    const float* wk = (const float*)d_in[2];
    const float* wv = (const float*)d_in[3];
    const float* wo = (const float*)d_in[4];
    float* out = (float*)d_out;

    __nv_bfloat16 *xs,*wqs,*wks,*wvs,*wos,*qs,*ks,*vt,*ps,*ctxs;
    float *v,*p,*ct,*st;
    cudaGetSymbolAddress((void**)&xs, g_xs);
    cudaGetSymbolAddress((void**)&wqs, g_wqs);
    cudaGetSymbolAddress((void**)&wks, g_wks);
    cudaGetSymbolAddress((void**)&wvs, g_wvs);
    cudaGetSymbolAddress((void**)&wos, g_wos);
    cudaGetSymbolAddress((void**)&qs, g_qs);
    cudaGetSymbolAddress((void**)&ks, g_ks);
    cudaGetSymbolAddress((void**)&v, g_v);
    cudaGetSymbolAddress((void**)&vt, g_vt);
    cudaGetSymbolAddress((void**)&p, g_p);
    cudaGetSymbolAddress((void**)&ps, g_ps);
    cudaGetSymbolAddress((void**)&ctxs, g_ctxs);
    cudaGetSymbolAddress((void**)&ct, g_cos);
    cudaGetSymbolAddress((void**)&st, g_sin);

    const int SMEM = 65536;
    cudaFuncSetAttribute(tgemm<0>, cudaFuncAttributeMaxDynamicSharedMemorySize, SMEM);
    cudaFuncSetAttribute(tgemm<1>, cudaFuncAttributeMaxDynamicSharedMemorySize, SMEM);
    cudaFuncSetAttribute(tgemm<2>, cudaFuncAttributeMaxDynamicSharedMemorySize, SMEM);

    // L1: rope  L2: conv(all)  L3-5: Q/K/V proj  L6: scores (ncu -s5 -c1 target)
    rope_tables_k<<<(S_*(D_/2))/256, 256>>>(ct, st);

    const int totChunks = (MTOT + 4*D_) * 256;    // rows * 256 chunks
    conv_split_all<<<totChunks/256, 256>>>((const float4*)x, xs,
                                           (const float4*)wq, wqs,
                                           (const float4*)wk, wks,
                                           (const float4*)wv, wvs,
                                           (const float4*)wo, wos);

    // projections: [8192,2048], logical K=6144, wA=2048, wB=4096
    dim3 gProj(D_/128, MTOT/128, 1);   // (16, 64)
    tgemm<1><<<gProj, 256, SMEM>>>(xs, 2*D_, wqs, 2*D_, nullptr, qs, 0,
                                   3*D_, D_, 2*D_, 1.f, 0, 0, 0, ct, st);
    tgemm<1><<<gProj, 256, SMEM>>>(xs, 2*D_, wks, 2*D_, nullptr, ks, 0,
                                   3*D_, D_, 2*D_, 1.f, 0, 0, 0, ct, st);
    tgemm<0><<<gProj, 256, SMEM>>>(xs, 2*D_, wvs, 2*D_, v, nullptr, D_,
                                   3*D_, D_, 2*D_, 1.f, 0, 0, 0, nullptr, nullptr);

    // scores: per (b,h) [1024,1024], logical K=384, wA=128, wB=256  (launch #6)
    const float alpha = 1.0f / sqrtf((float)D_);
    tgemm<0><<<dim3(8, 8, BH_), 256, SMEM>>>(qs, 2*HD_, ks, 2*HD_, p, nullptr, S_,
                                             3*HD_, HD_, 2*HD_, alpha,
                                             (size_t)S_*2*HD_, (size_t)S_*2*HD_,
                                             (size_t)S_*S_, nullptr, nullptr);

    vsplit_k<<<dim3(BH_, 32, 4), 256>>>(v, vt);
    softmax_split_k<<<BH_*S_, 256>>>(p, ps);

    // ctx: per (b,h) [1024,128], logical K=3072, wA=1024, wB=2048
    tgemm<2><<<dim3(1, 8, BH_), 256, SMEM>>>(ps, 2*S_, vt, 2*S_, nullptr, ctxs, 0,
                                             3*S_, S_, 2*S_, 1.f,
                                             (size_t)S_*2*S_, (size_t)HD_*2*S_, 0,
                                             nullptr, nullptr);

    // out = ctx @ wo^T
    tgemm<0><<<gProj, 256, SMEM>>>(ctxs, 2*D_, wos, 2*D_, out, nullptr, D_,
                                   3*D_, D_, 2*D_, 1.f, 0, 0, 0, nullptr, nullptr);
}

// round 8
// speedup vs baseline: 1.3455x; 1.0917x over previous
#include <cuda_runtime.h>
#include <cuda_bf16.h>
#include <math.h>
#include <stdint.h>

#define B_   8
#define S_   1024
#define D_   2048
#define H_   16
#define HD_  128
#define MTOT (B_*S_)
#define BH_  (B_*H_)

// split storage: [hi | lo] planes; logical K=3K via index wrap in the GEMM
__device__ __nv_bfloat16 g_xs  [(size_t)MTOT*2*D_];
__device__ __nv_bfloat16 g_wqs [(size_t)D_*2*D_];
__device__ __nv_bfloat16 g_wks [(size_t)D_*2*D_];
__device__ __nv_bfloat16 g_wvs [(size_t)D_*2*D_];
__device__ __nv_bfloat16 g_wos [(size_t)D_*2*D_];
__device__ __nv_bfloat16 g_qs  [(size_t)BH_*S_*2*HD_];
__device__ __nv_bfloat16 g_ks  [(size_t)BH_*S_*2*HD_];
__device__ float         g_v   [(size_t)MTOT*D_];
__device__ __nv_bfloat16 g_vt  [(size_t)BH_*HD_*2*S_];
__device__ float         g_p   [(size_t)BH_*S_*S_];
__device__ __nv_bfloat16 g_ps  [(size_t)BH_*S_*2*S_];
__device__ __nv_bfloat16 g_ctxs[(size_t)MTOT*2*D_];
__device__ float g_cos[(size_t)S_*(D_/2)];
__device__ float g_sin[(size_t)S_*(D_/2)];

__device__ __forceinline__ uint32_t smem_u32(const void* p) {
    uint32_t a;
    asm("{ .reg .u64 t; cvta.to.shared.u64 t, %1; cvt.u32.u64 %0, t; }" : "=r"(a) : "l"(p));
    return a;
}
__device__ __forceinline__ void cp16(uint32_t dst, const void* src) {
    asm volatile("cp.async.cg.shared.global [%0], [%1], 16;" :: "r"(dst), "l"(src));
}
#define CP_COMMIT() asm volatile("cp.async.commit_group;" ::: "memory")
#define CP_WAIT1()  asm volatile("cp.async.wait_group 1;" ::: "memory")

#define LDSM4(r, addr)                                                         \
    asm volatile("ldmatrix.sync.aligned.m8n8.x4.shared.b16 {%0,%1,%2,%3}, [%4];" \
        : "=r"((r)[0]),"=r"((r)[1]),"=r"((r)[2]),"=r"((r)[3]) : "r"(addr))

#define MMA(d, a, b0r, b1r)                                                    \
    asm volatile("mma.sync.aligned.m16n8k16.row.col.f32.bf16.bf16.f32 "        \
        "{%0,%1,%2,%3}, {%4,%5,%6,%7}, {%8,%9}, {%0,%1,%2,%3};"                \
        : "+f"((d)[0]),"+f"((d)[1]),"+f"((d)[2]),"+f"((d)[3])                  \
        : "r"((a)[0]),"r"((a)[1]),"r"((a)[2]),"r"((a)[3]), "r"(b0r),"r"(b1r))

__device__ __forceinline__ uint32_t pack_hi(float a, float b, float* la, float* lb) {
    __nv_bfloat162 p;
    p.x = __float2bfloat16(a); p.y = __float2bfloat16(b);
    *la = a - __bfloat162float(p.x);
    *lb = b - __bfloat162float(p.y);
    return *(uint32_t*)&p;
}
__device__ __forceinline__ uint32_t pack_bf2(float a, float b) {
    __nv_bfloat162 p;
    p.x = __float2bfloat16(a); p.y = __float2bfloat16(b);
    return *(uint32_t*)&p;
}

// smem tile: 128 rows x 64 bf16 (128B/row), SW128 swizzle ch^(row&7)
__device__ __forceinline__ void load_tile(uint32_t sbase, const __nv_bfloat16* g,
                                          int ld, int t) {
#pragma unroll
    for (int i = 0; i < 4; i++) {
        int lin = t + 256*i;                 // 0..1023 chunks
        int row = lin >> 3, ch = lin & 7;
        uint32_t sw = row*128 + ((ch ^ (row & 7)) << 4);
        cp16(sbase + sw, g + (size_t)row*ld + ch*8);
    }
}

// ===========================================================================
// mma.sync bf16 GEMM: C = alpha * A'[M,K3] @ B'[N,K3]^T
// CTA 128x128, BK=64, 3-stage cp.async (96KB smem), 8 warps (2Mx4N), warp 64x32
// Logical K3 = 3K on [hi|lo] storage (width 2K):
//   A col = k - (k>=wA ? wA : 0)   -> pattern (hi, hi, lo),  wA = K
//   B col = k - (k>=wB ? wB : 0)   -> pattern (hi, lo, hi),  wB = 2K
// EPI 0: fp32. EPI 1: RoPE+split -> [b,h,s,2*128]. EPI 2: split -> [8192,2*2048]
// ===========================================================================
template <int EPI>
__global__ __launch_bounds__(256) void tgemm(
    const __nv_bfloat16* __restrict__ A, int lda,
    const __nv_bfloat16* __restrict__ B, int ldb,
    float* __restrict__ Cf, __nv_bfloat16* __restrict__ Cs, int ldc,
    int K3, int wA, int wB, float alpha,
    size_t sA, size_t sB, size_t sC,
    const float* __restrict__ cosT, const float* __restrict__ sinT)
{
    extern __shared__ __align__(1024) char dsm[];
    const uint32_t smem0 = smem_u32(dsm);

    const int t = threadIdx.x, lane = t & 31, w = t >> 5;
    const int wm = w >> 2, wn = w & 3;
    const int z = blockIdx.z;
    const int m0 = blockIdx.y * 128, n0 = blockIdx.x * 128;
    const __nv_bfloat16* At = A + (size_t)z*sA + (size_t)m0*lda;
    const __nv_bfloat16* Bt = B + (size_t)z*sB + (size_t)n0*ldb;

    float acc[4][4][4];
#pragma unroll
    for (int i = 0; i < 4; i++)
#pragma unroll
        for (int j = 0; j < 4; j++)
#pragma unroll
            for (int c = 0; c < 4; c++) acc[i][j][c] = 0.f;

    const int NS = K3 / 64;
#pragma unroll
    for (int st = 0; st < 2; st++) {
        int k0 = st*64;
        int ka = k0 - (k0 >= wA ? wA : 0);
        int kb = k0 - (k0 >= wB ? wB : 0);
        load_tile(smem0 + st*32768,         At + ka, lda, t);
        load_tile(smem0 + st*32768 + 16384, Bt + kb, ldb, t);
        CP_COMMIT();
    }
    const int l15 = lane & 15, l16 = lane >> 4;

    int cbuf = 0, pbuf = 2;                       // s%3 and (s+2)%3
    for (int s = 0; s < NS; s++) {
        CP_WAIT1();
        __syncthreads();
        if (s + 2 < NS) {
            int k0 = (s+2)*64;
            int ka = k0 - (k0 >= wA ? wA : 0);
            int kb = k0 - (k0 >= wB ? wB : 0);
            load_tile(smem0 + pbuf*32768,         At + ka, lda, t);
            load_tile(smem0 + pbuf*32768 + 16384, Bt + kb, ldb, t);
        }
        CP_COMMIT();

        const uint32_t sAb = smem0 + cbuf*32768;
        const uint32_t sBb = sAb + 16384;
#pragma unroll
        for (int ks = 0; ks < 4; ks++) {
            uint32_t a[4][4], b[2][4];
            const int ch = ks*2 + l16;
#pragma unroll
            for (int mi = 0; mi < 4; mi++) {
                int r = wm*64 + mi*16 + l15;
                LDSM4(a[mi], sAb + r*128 + ((ch ^ (r & 7)) << 4));
            }
#pragma unroll
            for (int nj = 0; nj < 2; nj++) {
                int r = wn*32 + nj*16 + l15;
                LDSM4(b[nj], sBb + r*128 + ((ch ^ (r & 7)) << 4));
            }
#pragma unroll
            for (int mi = 0; mi < 4; mi++)
#pragma unroll
                for (int ni = 0; ni < 4; ni++)
                    MMA(acc[mi][ni], a[mi], b[ni >> 1][ni & 1], b[ni >> 1][(ni & 1) + 2]);
        }
        cbuf = (cbuf == 2) ? 0 : cbuf + 1;
        pbuf = (pbuf == 2) ? 0 : pbuf + 1;
    }

    // ------------------------------ epilogue -------------------------------
    const int gi = lane >> 2, t4 = lane & 3;
#pragma unroll
    for (int mi = 0; mi < 4; mi++) {
#pragma unroll
        for (int half = 0; half < 2; half++) {
            const int row = m0 + wm*64 + mi*16 + gi + half*8;
            if (EPI == 0) {
                float* dst = Cf + (size_t)z*sC + (size_t)row*ldc + n0;
#pragma unroll
                for (int ni = 0; ni < 4; ni++) {
                    int lc = wn*32 + ni*8 + t4*2;
                    *(float2*)(dst + lc) = make_float2(acc[mi][ni][half*2]   * alpha,
                                                       acc[mi][ni][half*2+1] * alpha);
                }
            } else if (EPI == 1) {
                const int pos = row & (S_-1), bb = row >> 10;
                const float* cr = cosT + (size_t)pos*(D_/2);
                const float* sr = sinT + (size_t)pos*(D_/2);
#pragma unroll
                for (int ni = 0; ni < 4; ni++) {
                    int gc = n0 + wn*32 + ni*8 + t4*2;   // global hidden col
                    int h = gc >> 7, ch128 = gc & 127;
                    int fi = gc >> 1;
                    float c = cr[fi], sn = sr[fi];
                    float v0 = acc[mi][ni][half*2], v1 = acc[mi][ni][half*2+1];
                    float r0 = v0*c - v1*sn, r1 = v0*sn + v1*c;
                    float la, lb;
                    uint32_t hi = pack_hi(r0, r1, &la, &lb);
                    uint32_t lo = pack_bf2(la, lb);
                    __nv_bfloat16* dst = Cs + ((size_t)(bb*H_ + h)*S_ + pos)*(2*HD_) + ch128;
                    *(uint32_t*)(dst)       = hi;
                    *(uint32_t*)(dst + HD_) = lo;
                }
            } else {
                const int bb = z >> 4, h = z & 15;
                __nv_bfloat16* dst = Cs + (size_t)(bb*S_ + row)*(2*D_) + h*HD_;
#pragma unroll
                for (int ni = 0; ni < 4; ni++) {
                    int lc = wn*32 + ni*8 + t4*2;
                    float la, lb;
                    uint32_t hi = pack_hi(acc[mi][ni][half*2], acc[mi][ni][half*2+1],
                                          &la, &lb);
                    uint32_t lo = pack_bf2(la, lb);
                    *(uint32_t*)(dst + lc)      = hi;
                    *(uint32_t*)(dst + lc + D_) = lo;
                }
            }
        }
    }
}

// fp32 -> [hi|lo] bf16 for x + 4 weights in ONE launch (row-partitioned)
__global__ __launch_bounds__(256) void conv_split_all(
    const float4* __restrict__ x,  __nv_bfloat16* __restrict__ xs,
    const float4* __restrict__ w0, __nv_bfloat16* __restrict__ o0,
    const float4* __restrict__ w1, __nv_bfloat16* __restrict__ o1,
    const float4* __restrict__ w2, __nv_bfloat16* __restrict__ o2,
    const float4* __restrict__ w3, __nv_bfloat16* __restrict__ o3)
{
    int i = blockIdx.x*256 + threadIdx.x;           // chunk of 8 elems
    int row = i >> 8, cj = i & 255;                 // 256 chunks per 2048-row
    const float4* src; __nv_bfloat16* dst; int r;
    if (row < MTOT)            { src = x;  dst = xs; r = row; }
    else {
        int wrow = row - MTOT, wi = wrow >> 11; r = wrow & (D_-1);
        if      (wi == 0) { src = w0; dst = o0; }
        else if (wi == 1) { src = w1; dst = o1; }
        else if (wi == 2) { src = w2; dst = o2; }
        else              { src = w3; dst = o3; }
    }
    // row = 512 float4s; chunk cj covers float4 indices [cj*2, cj*2+2)
    float4 v0 = src[(size_t)r*512 + cj*2], v1 = src[(size_t)r*512 + cj*2 + 1];
    float f[8] = {v0.x,v0.y,v0.z,v0.w,v1.x,v1.y,v1.z,v1.w};
    uint32_t hh[4], ll[4];
#pragma unroll
    for (int j = 0; j < 4; j++) {
        float la, lb;
        hh[j] = pack_hi(f[2*j], f[2*j+1], &la, &lb);
        ll[j] = pack_bf2(la, lb);
    }
    __nv_bfloat16* d = dst + (size_t)r*(2*D_) + cj*8;
    *(uint4*)d        = make_uint4(hh[0],hh[1],hh[2],hh[3]);
    *(uint4*)(d + D_) = make_uint4(ll[0],ll[1],ll[2],ll[3]);
}

// V [b,s,h,hd] fp32 -> VT [bh,n,2*1024] = [hi|lo]
__global__ __launch_bounds__(256) void vsplit_k(
    const float* __restrict__ V, __nv_bfloat16* __restrict__ VT)
{
    __shared__ float tile[32][33];
    const int bh = blockIdx.x, b = bh >> 4, h = bh & 15;
    const int k0 = blockIdx.y*32, n0 = blockIdx.z*32;
    const int r = threadIdx.x >> 5, c = threadIdx.x & 31;
#pragma unroll
    for (int i = 0; i < 4; i++)
        tile[r + i*8][c] = V[((size_t)(b*S_ + k0 + r + i*8))*D_ + h*HD_ + n0 + c];
    __syncthreads();
#pragma unroll
    for (int i = 0; i < 4; i++) {
        int n = n0 + r + i*8;
        float v = tile[c][r + i*8];
        __nv_bfloat16 hi = __float2bfloat16(v);
        __nv_bfloat16 lo = __float2bfloat16(v - __bfloat162float(hi));
        __nv_bfloat16* dst = VT + ((size_t)bh*HD_ + n)*(2*S_) + k0 + c;
        dst[0]  = hi;
        dst[S_] = lo;
    }
}

// softmax over 1024 + split-write [row, 2*1024] = [hi|lo]
__global__ __launch_bounds__(256) void softmax_split_k(
    const float* __restrict__ P, __nv_bfloat16* __restrict__ PS)
{
    const float4* row = (const float4*)(P + (size_t)blockIdx.x*S_);
    const int t = threadIdx.x;
    __shared__ float red[256];
    float4 v = row[t];
    float m = fmaxf(fmaxf(v.x, v.y), fmaxf(v.z, v.w));
    red[t] = m; __syncthreads();
    for (int s = 128; s > 0; s >>= 1) { if (t < s) red[t] = fmaxf(red[t], red[t+s]); __syncthreads(); }
    m = red[0]; __syncthreads();
    v.x = expf(v.x - m); v.y = expf(v.y - m);
    v.z = expf(v.z - m); v.w = expf(v.w - m);
    red[t] = v.x + v.y + v.z + v.w; __syncthreads();
    for (int s = 128; s > 0; s >>= 1) { if (t < s) red[t] += red[t+s]; __syncthreads(); }
    const float inv = 1.f / red[0];
    float f[4] = { v.x*inv, v.y*inv, v.z*inv, v.w*inv };
    float la0, lb0, la1, lb1;
    uint32_t h0 = pack_hi(f[0], f[1], &la0, &lb0);
    uint32_t h1 = pack_hi(f[2], f[3], &la1, &lb1);
    __nv_bfloat16* dst = PS + (size_t)blockIdx.x*(2*S_) + t*4;
    *(uint2*)dst        = make_uint2(h0, h1);
    *(uint2*)(dst + S_) = make_uint2(pack_bf2(la0, lb0), pack_bf2(la1, lb1));
}

__global__ void rope_tables_k(float* __restrict__ cosT, float* __restrict__ sinT) {
    int idx = blockIdx.x*blockDim.x + threadIdx.x;
    int pos = idx >> 10, f = idx & 1023;
    double inv = exp(-(double)(2*f)/(double)D_ * 9.210340371976184);
    double a = (double)pos * inv;
    cosT[idx] = (float)cos(a);
    sinT[idx] = (float)sin(a);
}

extern "C" void kernel_launch(void* const* d_in, const int* in_sizes, int n_in,
                              void* d_out, int out_size) {
    const float* x  = (const float*)d_in[0];
    const float* wq = (const float*)d_in[1];
    const float* wk = (const float*)d_in[2];
    const float* wv = (const float*)d_in[3];
    const float* wo = (const float*)d_in[4];
    float* out = (float*)d_out;

    __nv_bfloat16 *xs,*wqs,*wks,*wvs,*wos,*qs,*ks,*vt,*ps,*ctxs;
    float *v,*p,*ct,*st;
    cudaGetSymbolAddress((void**)&xs, g_xs);
    cudaGetSymbolAddress((void**)&wqs, g_wqs);
    cudaGetSymbolAddress((void**)&wks, g_wks);
    cudaGetSymbolAddress((void**)&wvs, g_wvs);
    cudaGetSymbolAddress((void**)&wos, g_wos);
    cudaGetSymbolAddress((void**)&qs, g_qs);
    cudaGetSymbolAddress((void**)&ks, g_ks);
    cudaGetSymbolAddress((void**)&v, g_v);
    cudaGetSymbolAddress((void**)&vt, g_vt);
    cudaGetSymbolAddress((void**)&p, g_p);
    cudaGetSymbolAddress((void**)&ps, g_ps);
    cudaGetSymbolAddress((void**)&ctxs, g_ctxs);
    cudaGetSymbolAddress((void**)&ct, g_cos);
    cudaGetSymbolAddress((void**)&st, g_sin);

    const int SMEM = 98304;     // 3 stages x 32KB
    cudaFuncSetAttribute(tgemm<0>, cudaFuncAttributeMaxDynamicSharedMemorySize, SMEM);
    cudaFuncSetAttribute(tgemm<1>, cudaFuncAttributeMaxDynamicSharedMemorySize, SMEM);
    cudaFuncSetAttribute(tgemm<2>, cudaFuncAttributeMaxDynamicSharedMemorySize, SMEM);

    // L1: rope  L2: conv(all)  L3-5: Q/K/V proj  L6: scores (ncu -s5 -c1 target)
    rope_tables_k<<<(S_*(D_/2))/256, 256>>>(ct, st);

    const int totChunks = (MTOT + 4*D_) * 256;    // rows * 256 chunks
    conv_split_all<<<totChunks/256, 256>>>((const float4*)x, xs,
                                           (const float4*)wq, wqs,
                                           (const float4*)wk, wks,
                                           (const float4*)wv, wvs,
                                           (const float4*)wo, wos);

    // projections: [8192,2048], logical K=6144, wA=2048, wB=4096
    dim3 gProj(D_/128, MTOT/128, 1);   // (16, 64)
    tgemm<1><<<gProj, 256, SMEM>>>(xs, 2*D_, wqs, 2*D_, nullptr, qs, 0,
                                   3*D_, D_, 2*D_, 1.f, 0, 0, 0, ct, st);
    tgemm<1><<<gProj, 256, SMEM>>>(xs, 2*D_, wks, 2*D_, nullptr, ks, 0,
                                   3*D_, D_, 2*D_, 1.f, 0, 0, 0, ct, st);
    tgemm<0><<<gProj, 256, SMEM>>>(xs, 2*D_, wvs, 2*D_, v, nullptr, D_,
                                   3*D_, D_, 2*D_, 1.f, 0, 0, 0, nullptr, nullptr);

    // scores: per (b,h) [1024,1024], logical K=384, wA=128, wB=256  (launch #6)
    const float alpha = 1.0f / sqrtf((float)D_);
    tgemm<0><<<dim3(8, 8, BH_), 256, SMEM>>>(qs, 2*HD_, ks, 2*HD_, p, nullptr, S_,
                                             3*HD_, HD_, 2*HD_, alpha,
                                             (size_t)S_*2*HD_, (size_t)S_*2*HD_,
                                             (size_t)S_*S_, nullptr, nullptr);

    vsplit_k<<<dim3(BH_, 32, 4), 256>>>(v, vt);
    softmax_split_k<<<BH_*S_, 256>>>(p, ps);

    // ctx: per (b,h) [1024,128], logical K=3072, wA=1024, wB=2048
    tgemm<2><<<dim3(1, 8, BH_), 256, SMEM>>>(ps, 2*S_, vt, 2*S_, nullptr, ctxs, 0,
                                             3*S_, S_, 2*S_, 1.f,
                                             (size_t)S_*2*S_, (size_t)HD_*2*S_, 0,
                                             nullptr, nullptr);

    // out = ctx @ wo^T
    tgemm<0><<<gProj, 256, SMEM>>>(ctxs, 2*D_, wos, 2*D_, out, nullptr, D_,
                                   3*D_, D_, 2*D_, 1.f, 0, 0, 0, nullptr, nullptr);
}